// round 2
// baseline (speedup 1.0000x reference)
#include <cuda_runtime.h>
#include <cstdint>
#include <cstddef>

#define DI __device__ __forceinline__

// ---------------- problem constants ----------------
constexpr int BATCH = 131072;
constexpr int HD    = 128;       // H == IN == 128
constexpr int KTOT  = 256;       // x(128) ++ h_prev(128)
constexpr int BM    = 256;       // batch rows per CTA
constexpr int BN    = 128;       // output gate-columns per CTA (= 32 j's x 4 gates)
constexpr int KC    = 32;        // fp32 K per stage
constexpr int NKCH  = KTOT / KC; // 8
constexpr int NTHR  = 512;       // 16 warps: 4(m) x 4(n)

// smem (floats)
constexpr int APITCH = 36;                    // padded pitch (conflict-free)
constexpr int A_FL   = BM * APITCH;           // 9216
constexpr int B_FL   = BN * APITCH;           // 4608
constexpr int STG_FL = A_FL + B_FL;           // 13824
constexpr int ZPITCH = 136;                   // epilogue pitch (16B-aligned rows)
constexpr int Z_FL   = BM * ZPITCH;           // 34816
constexpr int SM_BYTES = Z_FL * 4;            // 139264 (> 2*STG_FL*4 = 110592)

// weights: transposed+interleaved to [n=512][k=256], n = 4*j + gate, tf32-rounded
static __device__ float g_Bt[512 * KTOT];

// ---------------- PTX helpers ----------------
DI void cp_async16(void* dst, const void* src) {
    uint32_t a;
    asm("{ .reg .u64 t; cvta.to.shared.u64 t, %1; cvt.u32.u64 %0, t; }" : "=r"(a) : "l"(dst));
    asm volatile("cp.async.cg.shared.global [%0], [%1], 16;" :: "r"(a), "l"(src));
}
DI void cp_commit() { asm volatile("cp.async.commit_group;" ::: "memory"); }
template<int N> DI void cp_wait() { asm volatile("cp.async.wait_group %0;" :: "n"(N) : "memory"); }

DI uint32_t cvt_tf32(float v) {
    uint32_t t;
    asm("cvt.rna.tf32.f32 %0, %1;" : "=r"(t) : "f"(v));
    return t;
}
DI void mma8(float* d, const uint32_t* a, const uint32_t* b) {
    asm volatile("mma.sync.aligned.m16n8k8.row.col.f32.tf32.tf32.f32 "
        "{%0,%1,%2,%3}, {%4,%5,%6,%7}, {%8,%9}, {%0,%1,%2,%3};"
        : "+f"(d[0]), "+f"(d[1]), "+f"(d[2]), "+f"(d[3])
        : "r"(a[0]), "r"(a[1]), "r"(a[2]), "r"(a[3]), "r"(b[0]), "r"(b[1]));
}
DI float fast_sigmoid(float z) { return 1.0f / (1.0f + __expf(-z)); }
DI float fast_tanh(float z)    { float e = __expf(-2.0f * z); return (1.0f - e) / (1.0f + e); }

// ---------------- prologue: transpose + interleave + tf32-round weights ----------------
__global__ void prep_weights_kernel(
    const float* __restrict__ Wi, const float* __restrict__ Ui,
    const float* __restrict__ Wf, const float* __restrict__ Uf,
    const float* __restrict__ Wg, const float* __restrict__ Ug,
    const float* __restrict__ Wo, const float* __restrict__ Uo)
{
    int idx = blockIdx.x * blockDim.x + threadIdx.x;  // 0 .. 131071
    int k    = idx & 255;
    int row  = idx >> 8;          // n = 4*j + gate, 0..511
    int j    = row >> 2;
    int gate = row & 3;
    const float* W = (gate == 0) ? Wi : (gate == 1) ? Wf : (gate == 2) ? Wg : Wo;
    const float* U = (gate == 0) ? Ui : (gate == 1) ? Uf : (gate == 2) ? Ug : Uo;
    float v = (k < HD) ? W[k * HD + j] : U[(k - HD) * HD + j];
    reinterpret_cast<uint32_t*>(g_Bt)[row * KTOT + k] = cvt_tf32(v);
}

// ---------------- stage loader ----------------
DI void load_stage(float* sm, int buf, int s,
                   const float* __restrict__ x, const float* __restrict__ hp,
                   int m0, int n0w, int tid)
{
    float* As = sm + buf * STG_FL;
    float* Bs = As + A_FL;
    const float* asrc = (s < 4) ? x : hp;
    int kc = (s & 3) * KC;            // column offset within 128-wide source
    // A: 256 rows x 32 f32 = 2048 float4 -> 4 per thread
    #pragma unroll
    for (int i = 0; i < 4; i++) {
        int t  = tid + i * NTHR;
        int r  = t >> 3, c4 = t & 7;
        cp_async16(As + r * APITCH + c4 * 4,
                   asrc + (size_t)(m0 + r) * HD + kc + c4 * 4);
    }
    // B: 128 rows x 32 f32 = 1024 float4 -> 2 per thread
    #pragma unroll
    for (int i = 0; i < 2; i++) {
        int t  = tid + i * NTHR;
        int r  = t >> 3, c4 = t & 7;
        cp_async16(Bs + r * APITCH + c4 * 4,
                   g_Bt + (size_t)(n0w + r) * KTOT + s * KC + c4 * 4);
    }
    cp_commit();
}

// ---------------- main fused kernel ----------------
__global__ void __launch_bounds__(NTHR, 1) lstm_kernel(
    const float* __restrict__ x, const float* __restrict__ hp,
    const float* __restrict__ cprev,
    const float* __restrict__ bi, const float* __restrict__ bf,
    const float* __restrict__ bg, const float* __restrict__ bo,
    float* __restrict__ out)
{
    extern __shared__ float sm[];
    const int tid  = threadIdx.x;
    const int lane = tid & 31;
    const int wid  = tid >> 5;
    const int wm   = wid & 3;        // warp m-index (4)
    const int wn   = wid >> 2;       // warp n-index (4)
    const int q    = lane & 3;
    const int g    = lane >> 2;

    const int mblk = blockIdx.x >> 2;
    const int nblk = blockIdx.x & 3;
    const int m0   = mblk * BM;
    const int n0w  = nblk * BN;      // weight-row base (interleaved n)
    const int j0   = nblk * 32;      // hidden-unit base

    float acc[4][4][4];
    #pragma unroll
    for (int a = 0; a < 4; a++)
        #pragma unroll
        for (int b = 0; b < 4; b++)
            #pragma unroll
            for (int c = 0; c < 4; c++) acc[a][b][c] = 0.0f;

    // ---- pipelined GEMM over 8 K-chunks ----
    load_stage(sm, 0, 0, x, hp, m0, n0w, tid);
    load_stage(sm, 1, 1, x, hp, m0, n0w, tid);

    #pragma unroll
    for (int s = 0; s < NKCH; s++) {
        const int buf = s & 1;
        if (s < NKCH - 1) cp_wait<1>(); else cp_wait<0>();
        __syncthreads();

        const float*    As = sm + buf * STG_FL;
        const uint32_t* Bs = reinterpret_cast<const uint32_t*>(As + A_FL);

        #pragma unroll
        for (int ks = 0; ks < 4; ks++) {
            const int k0 = ks * 8;
            uint32_t afr[4][4];
            #pragma unroll
            for (int mt = 0; mt < 4; mt++) {
                const int r = wm * 64 + mt * 16 + g;
                afr[mt][0] = cvt_tf32(As[r * APITCH + k0 + q]);
                afr[mt][1] = cvt_tf32(As[(r + 8) * APITCH + k0 + q]);
                afr[mt][2] = cvt_tf32(As[r * APITCH + k0 + q + 4]);
                afr[mt][3] = cvt_tf32(As[(r + 8) * APITCH + k0 + q + 4]);
            }
            uint32_t bfr[4][2];
            #pragma unroll
            for (int nt = 0; nt < 4; nt++) {
                const int n = wn * 32 + nt * 8 + g;
                bfr[nt][0] = Bs[n * APITCH + k0 + q];
                bfr[nt][1] = Bs[n * APITCH + k0 + q + 4];
            }
            #pragma unroll
            for (int mt = 0; mt < 4; mt++)
                #pragma unroll
                for (int nt = 0; nt < 4; nt++)
                    mma8(acc[mt][nt], afr[mt], bfr[nt]);
        }

        __syncthreads();
        if (s + 2 < NKCH) load_stage(sm, buf, s + 2, x, hp, m0, n0w, tid);
    }

    // ---- spill accumulators to smem z-tile [row][n], pitch ZPITCH ----
    __syncthreads();   // everyone done reading stage buffers (overlay reuse)
    #pragma unroll
    for (int mt = 0; mt < 4; mt++) {
        const int r0 = wm * 64 + mt * 16 + g;
        #pragma unroll
        for (int nt = 0; nt < 4; nt++) {
            const int n0 = wn * 32 + nt * 8 + 2 * q;
            *reinterpret_cast<float2*>(&sm[r0 * ZPITCH + n0]) =
                make_float2(acc[mt][nt][0], acc[mt][nt][1]);
            *reinterpret_cast<float2*>(&sm[(r0 + 8) * ZPITCH + n0]) =
                make_float2(acc[mt][nt][2], acc[mt][nt][3]);
        }
    }
    __syncthreads();

    // ---- fused LSTM epilogue: 256 rows x 32 j's ----
    const int jl = lane;                 // 0..31 (tid&31)
    const int jg = j0 + jl;
    const float Bi = __ldg(bi + jg);
    const float Bf = __ldg(bf + jg);
    const float Bg = __ldg(bg + jg);
    const float Bo = __ldg(bo + jg);
    float* hout = out;
    float* cout = out + (size_t)BATCH * HD;

    #pragma unroll 4
    for (int it = 0; it < 16; it++) {
        const int row = it * 16 + wid;
        float4 z = *reinterpret_cast<const float4*>(&sm[row * ZPITCH + 4 * jl]);
        const float zi = z.x + Bi;
        const float zf = z.y + Bf;
        const float zg = z.z + Bg;
        const float zo = z.w + Bo;
        const float ig = fast_sigmoid(zi);
        const float fg = fast_sigmoid(zf);
        const float og = fast_sigmoid(zo);
        const float cc = fast_tanh(zg);
        const size_t go = (size_t)(m0 + row) * HD + jg;
        const float c0 = __ldg(cprev + go);
        const float cn = fg * c0 + ig * cc;
        const float hn = og * fast_tanh(cn);
        hout[go] = hn;
        cout[go] = cn;
    }
}

// ---------------- launch ----------------
extern "C" void kernel_launch(void* const* d_in, const int* in_sizes, int n_in,
                              void* d_out, int out_size)
{
    const float* x  = (const float*)d_in[0];
    const float* hp = (const float*)d_in[1];
    const float* cp = (const float*)d_in[2];
    const float* Wi = (const float*)d_in[3];
    const float* Ui = (const float*)d_in[4];
    const float* bi = (const float*)d_in[5];
    const float* Wf = (const float*)d_in[6];
    const float* Uf = (const float*)d_in[7];
    const float* bf = (const float*)d_in[8];
    const float* Wg = (const float*)d_in[9];
    const float* Ug = (const float*)d_in[10];
    const float* bg = (const float*)d_in[11];
    const float* Wo = (const float*)d_in[12];
    const float* Uo = (const float*)d_in[13];
    const float* bo = (const float*)d_in[14];
    float* out = (float*)d_out;

    cudaFuncSetAttribute(lstm_kernel, cudaFuncAttributeMaxDynamicSharedMemorySize, SM_BYTES);

    prep_weights_kernel<<<256, 512>>>(Wi, Ui, Wf, Uf, Wg, Ug, Wo, Uo);
    lstm_kernel<<<(BATCH / BM) * 4, NTHR, SM_BYTES>>>(x, hp, cp, bi, bf, bg, bo, out);
}

// round 3
// speedup vs baseline: 1.0988x; 1.0988x over previous
#include <cuda_runtime.h>
#include <cstdint>
#include <cstddef>

#define DI __device__ __forceinline__

// ---------------- problem constants ----------------
constexpr int BATCH = 131072;
constexpr int HD    = 128;       // H == IN == 128
constexpr int KTOT  = 256;       // x(128) ++ h_prev(128)
constexpr int BM    = 256;       // batch rows per CTA
constexpr int BN    = 128;       // output gate-columns per CTA (= 32 j's x 4 gates)
constexpr int KC    = 32;        // fp32 K per stage
constexpr int NKCH  = KTOT / KC; // 8
constexpr int NTHR  = 512;       // 16 warps: 4(m) x 4(n)
constexpr int NSTG  = 3;         // pipeline depth

// smem (floats)
constexpr int APITCH = 36;                    // A pitch: bank = 4g+q, conflict-free
constexpr int BPITCH = 40;                    // B pitch: dbank(8B) = 4g+q, conflict-free LDS.64
constexpr int A_FL   = BM * APITCH;           // 9216
constexpr int B_FL   = BN * BPITCH;           // 5120
constexpr int STG_FL = A_FL + B_FL;           // 14336
constexpr int ZPITCH = 136;
constexpr int Z_FL   = BM * ZPITCH;           // 34816 fl = 139264 B
constexpr int SM_BYTES = NSTG * STG_FL * 4;   // 172032 B (z-tile overlays: 139264 <= 172032)

// weights: transposed + gate-interleaved (n = 4*j + gate) + fragment-pair-permuted k,
// tf32(rna)-rounded. [n=512][k'=256]
static __device__ float g_Bt[512 * KTOT];

// ---------------- PTX helpers ----------------
DI void cp_async16(void* dst, const void* src) {
    uint32_t a;
    asm("{ .reg .u64 t; cvta.to.shared.u64 t, %1; cvt.u32.u64 %0, t; }" : "=r"(a) : "l"(dst));
    asm volatile("cp.async.cg.shared.global [%0], [%1], 16;" :: "r"(a), "l"(src));
}
DI void cp_commit() { asm volatile("cp.async.commit_group;" ::: "memory"); }
template<int N> DI void cp_wait() { asm volatile("cp.async.wait_group %0;" :: "n"(N) : "memory"); }

DI uint32_t cvt_tf32(float v) {
    uint32_t t;
    asm("cvt.rna.tf32.f32 %0, %1;" : "=r"(t) : "f"(v));
    return t;
}
DI void mma8(float* d, const uint32_t* a, const uint32_t* b) {
    asm volatile("mma.sync.aligned.m16n8k8.row.col.f32.tf32.tf32.f32 "
        "{%0,%1,%2,%3}, {%4,%5,%6,%7}, {%8,%9}, {%0,%1,%2,%3};"
        : "+f"(d[0]), "+f"(d[1]), "+f"(d[2]), "+f"(d[3])
        : "r"(a[0]), "r"(a[1]), "r"(a[2]), "r"(a[3]), "r"(b[0]), "r"(b[1]));
}
DI float fast_sigmoid(float z) { return 1.0f / (1.0f + __expf(-z)); }
DI float fast_tanh(float z)    { float e = __expf(-2.0f * z); return (1.0f - e) / (1.0f + e); }

// ---------------- prologue: transpose + interleave + permute + tf32-round ----------------
// g_Bt[n][kp]: kp = chunk*32 + ks*8 + q*2 + h  <->  k = chunk*32 + ks*8 + q + 4*h
__global__ void prep_weights_kernel(
    const float* __restrict__ Wi, const float* __restrict__ Ui,
    const float* __restrict__ Wf, const float* __restrict__ Uf,
    const float* __restrict__ Wg, const float* __restrict__ Ug,
    const float* __restrict__ Wo, const float* __restrict__ Uo)
{
    int idx = blockIdx.x * blockDim.x + threadIdx.x;  // 0 .. 131071
    int kp   = idx & 255;
    int row  = idx >> 8;          // n = 4*j + gate
    int j    = row >> 2;
    int gate = row & 3;
    int chunk = kp >> 5;
    int r5    = kp & 31;
    int ks    = r5 >> 3;
    int t     = r5 & 7;
    int q     = t >> 1;
    int h     = t & 1;
    int k     = chunk * 32 + ks * 8 + q + 4 * h;
    const float* W = (gate == 0) ? Wi : (gate == 1) ? Wf : (gate == 2) ? Wg : Wo;
    const float* U = (gate == 0) ? Ui : (gate == 1) ? Uf : (gate == 2) ? Ug : Uo;
    float v = (k < HD) ? W[k * HD + j] : U[(k - HD) * HD + j];
    reinterpret_cast<uint32_t*>(g_Bt)[row * KTOT + kp] = cvt_tf32(v);
}

// ---------------- stage loader ----------------
DI void load_stage(float* sm, int buf, int s,
                   const float* __restrict__ x, const float* __restrict__ hp,
                   int m0, int n0w, int tid)
{
    float* As = sm + buf * STG_FL;
    float* Bs = As + A_FL;
    const float* asrc = (s < 4) ? x : hp;
    int kc = (s & 3) * KC;
    // A: 256 rows x 32 f32 = 2048 float4 -> 4 per thread (natural k order)
    #pragma unroll
    for (int i = 0; i < 4; i++) {
        int t  = tid + i * NTHR;
        int r  = t >> 3, c4 = t & 7;
        cp_async16(As + r * APITCH + c4 * 4,
                   asrc + (size_t)(m0 + r) * HD + kc + c4 * 4);
    }
    // B: 128 rows x 32 f32 = 1024 float4 -> 2 per thread (pre-permuted k order)
    #pragma unroll
    for (int i = 0; i < 2; i++) {
        int t  = tid + i * NTHR;
        int r  = t >> 3, c4 = t & 7;
        cp_async16(Bs + r * BPITCH + c4 * 4,
                   g_Bt + (size_t)(n0w + r) * KTOT + s * KC + c4 * 4);
    }
    cp_commit();
}

// ---------------- main fused kernel ----------------
__global__ void __launch_bounds__(NTHR, 1) lstm_kernel(
    const float* __restrict__ x, const float* __restrict__ hp,
    const float* __restrict__ cprev,
    const float* __restrict__ bi, const float* __restrict__ bf,
    const float* __restrict__ bg, const float* __restrict__ bo,
    float* __restrict__ out)
{
    extern __shared__ float sm[];
    const int tid  = threadIdx.x;
    const int lane = tid & 31;
    const int wid  = tid >> 5;
    const int wm   = wid & 3;        // warp m-index (4)
    const int wn   = wid >> 2;       // warp n-index (4)
    const int q    = lane & 3;
    const int g    = lane >> 2;

    const int mblk = blockIdx.x >> 2;
    const int nblk = blockIdx.x & 3;
    const int m0   = mblk * BM;
    const int n0w  = nblk * BN;      // weight-row base (interleaved n)
    const int j0   = nblk * 32;      // hidden-unit base

    float acc[4][4][4];
    #pragma unroll
    for (int a = 0; a < 4; a++)
        #pragma unroll
        for (int b = 0; b < 4; b++)
            #pragma unroll
            for (int c = 0; c < 4; c++) acc[a][b][c] = 0.0f;

    // ---- 3-deep pipelined GEMM over 8 K-chunks, one barrier per stage ----
    load_stage(sm, 0, 0, x, hp, m0, n0w, tid);
    load_stage(sm, 1, 1, x, hp, m0, n0w, tid);

    #pragma unroll
    for (int s = 0; s < NKCH; s++) {
        const int buf = s % NSTG;
        if (s < NKCH - 1) cp_wait<1>(); else cp_wait<0>();
        __syncthreads();
        if (s + 2 < NKCH) load_stage(sm, (s + 2) % NSTG, s + 2, x, hp, m0, n0w, tid);

        const uint32_t* As = reinterpret_cast<const uint32_t*>(sm + buf * STG_FL);
        const uint32_t* Bs = As + A_FL;

        #pragma unroll
        for (int ks = 0; ks < 4; ks++) {
            const int k0 = ks * 8;
            uint32_t afr[4][4];
            #pragma unroll
            for (int mt = 0; mt < 4; mt++) {
                const int r = wm * 64 + mt * 16 + g;
                afr[mt][0] = As[r * APITCH + k0 + q];            // raw fp32 bits as tf32
                afr[mt][1] = As[(r + 8) * APITCH + k0 + q];
                afr[mt][2] = As[r * APITCH + k0 + q + 4];
                afr[mt][3] = As[(r + 8) * APITCH + k0 + q + 4];
            }
            uint32_t bfr[4][2];
            #pragma unroll
            for (int nt = 0; nt < 4; nt++) {
                const int n = wn * 32 + nt * 8 + g;
                // permuted layout: pair (k0+q, k0+q+4) is contiguous -> one LDS.64
                uint2 p = *reinterpret_cast<const uint2*>(&Bs[n * BPITCH + k0 + q * 2]);
                bfr[nt][0] = p.x;
                bfr[nt][1] = p.y;
            }
            #pragma unroll
            for (int mt = 0; mt < 4; mt++)
                #pragma unroll
                for (int nt = 0; nt < 4; nt++)
                    mma8(acc[mt][nt], afr[mt], bfr[nt]);
        }
    }

    // ---- spill accumulators to smem z-tile [row][n], pitch ZPITCH ----
    __syncthreads();   // all warps done reading stage buffers (overlay reuse)
    #pragma unroll
    for (int mt = 0; mt < 4; mt++) {
        const int r0 = wm * 64 + mt * 16 + g;
        #pragma unroll
        for (int nt = 0; nt < 4; nt++) {
            const int n0 = wn * 32 + nt * 8 + 2 * q;
            *reinterpret_cast<float2*>(&sm[r0 * ZPITCH + n0]) =
                make_float2(acc[mt][nt][0], acc[mt][nt][1]);
            *reinterpret_cast<float2*>(&sm[(r0 + 8) * ZPITCH + n0]) =
                make_float2(acc[mt][nt][2], acc[mt][nt][3]);
        }
    }
    __syncthreads();

    // ---- fused LSTM epilogue: 256 rows x 32 j's, fully coalesced ----
    const int jl = lane;
    const int jg = j0 + jl;
    const float Bi = __ldg(bi + jg);
    const float Bf = __ldg(bf + jg);
    const float Bg = __ldg(bg + jg);
    const float Bo = __ldg(bo + jg);
    float* hout = out;
    float* cout = out + (size_t)BATCH * HD;

    #pragma unroll 4
    for (int it = 0; it < 16; it++) {
        const int row = it * 16 + wid;
        float4 z = *reinterpret_cast<const float4*>(&sm[row * ZPITCH + 4 * jl]);
        const float zi = z.x + Bi;
        const float zf = z.y + Bf;
        const float zg = z.z + Bg;
        const float zo = z.w + Bo;
        const float ig = fast_sigmoid(zi);
        const float fg = fast_sigmoid(zf);
        const float og = fast_sigmoid(zo);
        const float cc = fast_tanh(zg);
        const size_t go = (size_t)(m0 + row) * HD + jg;
        const float c0 = __ldg(cprev + go);
        const float cn = fg * c0 + ig * cc;
        const float hn = og * fast_tanh(cn);
        hout[go] = hn;
        cout[go] = cn;
    }
}

// ---------------- launch ----------------
extern "C" void kernel_launch(void* const* d_in, const int* in_sizes, int n_in,
                              void* d_out, int out_size)
{
    const float* x  = (const float*)d_in[0];
    const float* hp = (const float*)d_in[1];
    const float* cp = (const float*)d_in[2];
    const float* Wi = (const float*)d_in[3];
    const float* Ui = (const float*)d_in[4];
    const float* bi = (const float*)d_in[5];
    const float* Wf = (const float*)d_in[6];
    const float* Uf = (const float*)d_in[7];
    const float* bf = (const float*)d_in[8];
    const float* Wg = (const float*)d_in[9];
    const float* Ug = (const float*)d_in[10];
    const float* bg = (const float*)d_in[11];
    const float* Wo = (const float*)d_in[12];
    const float* Uo = (const float*)d_in[13];
    const float* bo = (const float*)d_in[14];
    float* out = (float*)d_out;

    cudaFuncSetAttribute(lstm_kernel, cudaFuncAttributeMaxDynamicSharedMemorySize, SM_BYTES);

    prep_weights_kernel<<<256, 512>>>(Wi, Ui, Wf, Uf, Wg, Ug, Wo, Uo);
    lstm_kernel<<<(BATCH / BM) * 4, NTHR, SM_BYTES>>>(x, hp, cp, bi, bf, bg, bo, out);
}

// round 4
// speedup vs baseline: 1.3125x; 1.1945x over previous
#include <cuda_runtime.h>
#include <cstdint>
#include <cstddef>

#define DI __device__ __forceinline__

// ---------------- problem constants ----------------
constexpr int BATCH = 131072;
constexpr int HD    = 128;       // H == IN == 128
constexpr int KTOT  = 256;       // x(128) ++ h_prev(128)
constexpr int BM    = 256;       // batch rows per CTA
constexpr int BN    = 128;       // gate-columns per CTA (32 j's x 4 gates, interleaved)
constexpr int KC    = 32;        // fp32 K per stage
constexpr int NKCH  = KTOT / KC; // 8
constexpr int NTHR  = 1024;      // 32 warps: 8(m) x 4(n), warp tile 32x32
constexpr int NSTG  = 3;         // pipeline depth

// smem (floats)
constexpr int APITCH = 36;                    // A pitch: bank = 4g+q, conflict-free
constexpr int BPITCH = 40;                    // B pitch: dbank(8B) = 4g+q, conflict-free LDS.64
constexpr int A_FL   = BM * APITCH;           // 9216
constexpr int B_FL   = BN * BPITCH;           // 5120
constexpr int STG_FL = A_FL + B_FL;           // 14336
constexpr int ZPITCH = 136;
constexpr int Z_FL   = BM * ZPITCH;           // 34816 fl = 139264 B (overlays 3-stage region)
constexpr int SM_BYTES = NSTG * STG_FL * 4;   // 172032 B

// weights: transposed + gate-interleaved (n = 4*j + gate) + fragment-pair-permuted k,
// tf32(rna)-rounded. [n=512][k'=256]
static __device__ float g_Bt[512 * KTOT];

// ---------------- PTX helpers ----------------
DI void cp_async16(void* dst, const void* src) {
    uint32_t a;
    asm("{ .reg .u64 t; cvta.to.shared.u64 t, %1; cvt.u32.u64 %0, t; }" : "=r"(a) : "l"(dst));
    asm volatile("cp.async.cg.shared.global [%0], [%1], 16;" :: "r"(a), "l"(src));
}
DI void cp_commit() { asm volatile("cp.async.commit_group;" ::: "memory"); }
template<int N> DI void cp_wait() { asm volatile("cp.async.wait_group %0;" :: "n"(N) : "memory"); }

DI uint32_t cvt_tf32(float v) {
    uint32_t t;
    asm("cvt.rna.tf32.f32 %0, %1;" : "=r"(t) : "f"(v));
    return t;
}
DI void mma8(float* d, const uint32_t* a, const uint32_t* b) {
    asm volatile("mma.sync.aligned.m16n8k8.row.col.f32.tf32.tf32.f32 "
        "{%0,%1,%2,%3}, {%4,%5,%6,%7}, {%8,%9}, {%0,%1,%2,%3};"
        : "+f"(d[0]), "+f"(d[1]), "+f"(d[2]), "+f"(d[3])
        : "r"(a[0]), "r"(a[1]), "r"(a[2]), "r"(a[3]), "r"(b[0]), "r"(b[1]));
}
DI float fast_sigmoid(float z) { return 1.0f / (1.0f + __expf(-z)); }
DI float fast_tanh(float z)    { float e = __expf(-2.0f * z); return (1.0f - e) / (1.0f + e); }

// ---------------- prologue: transpose + interleave + permute + tf32-round ----------------
// g_Bt[n][kp]: kp = chunk*32 + ks*8 + q*2 + h  <->  k = chunk*32 + ks*8 + q + 4*h
__global__ void prep_weights_kernel(
    const float* __restrict__ Wi, const float* __restrict__ Ui,
    const float* __restrict__ Wf, const float* __restrict__ Uf,
    const float* __restrict__ Wg, const float* __restrict__ Ug,
    const float* __restrict__ Wo, const float* __restrict__ Uo)
{
    int idx = blockIdx.x * blockDim.x + threadIdx.x;  // 0 .. 131071
    int kp   = idx & 255;
    int row  = idx >> 8;          // n = 4*j + gate
    int j    = row >> 2;
    int gate = row & 3;
    int chunk = kp >> 5;
    int r5    = kp & 31;
    int ks    = r5 >> 3;
    int t     = r5 & 7;
    int q     = t >> 1;
    int h     = t & 1;
    int k     = chunk * 32 + ks * 8 + q + 4 * h;
    const float* W = (gate == 0) ? Wi : (gate == 1) ? Wf : (gate == 2) ? Wg : Wo;
    const float* U = (gate == 0) ? Ui : (gate == 1) ? Uf : (gate == 2) ? Ug : Uo;
    float v = (k < HD) ? W[k * HD + j] : U[(k - HD) * HD + j];
    reinterpret_cast<uint32_t*>(g_Bt)[row * KTOT + kp] = cvt_tf32(v);
}

// ---------------- stage loader ----------------
DI void load_stage(float* sm, int buf, int s,
                   const float* __restrict__ x, const float* __restrict__ hp,
                   int m0, int n0w, int tid)
{
    float* As = sm + buf * STG_FL;
    float* Bs = As + A_FL;
    const float* asrc = (s < 4) ? x : hp;
    int kc = (s & 3) * KC;
    // A: 256 rows x 32 f32 = 2048 float4 -> 2 per thread (natural k order)
    #pragma unroll
    for (int i = 0; i < 2; i++) {
        int t  = tid + i * NTHR;
        int r  = t >> 3, c4 = t & 7;
        cp_async16(As + r * APITCH + c4 * 4,
                   asrc + (size_t)(m0 + r) * HD + kc + c4 * 4);
    }
    // B: 128 rows x 32 f32 = 1024 float4 -> 1 per thread (pre-permuted k order)
    {
        int r  = tid >> 3, c4 = tid & 7;
        cp_async16(Bs + r * BPITCH + c4 * 4,
                   g_Bt + (size_t)(n0w + r) * KTOT + s * KC + c4 * 4);
    }
    cp_commit();
}

// ---------------- main fused kernel ----------------
__global__ void __launch_bounds__(NTHR, 1) lstm_kernel(
    const float* __restrict__ x, const float* __restrict__ hp,
    const float* __restrict__ cprev,
    const float* __restrict__ bi, const float* __restrict__ bf,
    const float* __restrict__ bg, const float* __restrict__ bo,
    float* __restrict__ out)
{
    extern __shared__ float sm[];
    const int tid  = threadIdx.x;
    const int lane = tid & 31;
    const int wid  = tid >> 5;
    const int wm   = wid & 7;        // warp m-index (8)
    const int wn   = wid >> 3;       // warp n-index (4)
    const int q    = lane & 3;
    const int g    = lane >> 2;

    const int mblk = blockIdx.x >> 2;
    const int nblk = blockIdx.x & 3;
    const int m0   = mblk * BM;
    const int n0w  = nblk * BN;      // weight-row base (interleaved n)
    const int j0   = nblk * 32;      // hidden-unit base

    float acc[2][4][4];
    #pragma unroll
    for (int a = 0; a < 2; a++)
        #pragma unroll
        for (int b = 0; b < 4; b++)
            #pragma unroll
            for (int c = 0; c < 4; c++) acc[a][b][c] = 0.0f;

    // ---- 3-deep pipelined GEMM over 8 K-chunks, one barrier per stage ----
    load_stage(sm, 0, 0, x, hp, m0, n0w, tid);
    load_stage(sm, 1, 1, x, hp, m0, n0w, tid);

    #pragma unroll
    for (int s = 0; s < NKCH; s++) {
        const int buf = s % NSTG;
        if (s < NKCH - 1) cp_wait<1>(); else cp_wait<0>();
        __syncthreads();
        if (s + 2 < NKCH) load_stage(sm, (s + 2) % NSTG, s + 2, x, hp, m0, n0w, tid);

        const uint32_t* As = reinterpret_cast<const uint32_t*>(sm + buf * STG_FL);
        const uint32_t* Bs = As + A_FL;

        #pragma unroll
        for (int ks = 0; ks < 4; ks++) {
            const int k0 = ks * 8;
            uint32_t afr[2][4];
            #pragma unroll
            for (int mt = 0; mt < 2; mt++) {
                const int r = wm * 32 + mt * 16 + g;
                afr[mt][0] = As[r * APITCH + k0 + q];            // raw fp32 bits as tf32
                afr[mt][1] = As[(r + 8) * APITCH + k0 + q];
                afr[mt][2] = As[r * APITCH + k0 + q + 4];
                afr[mt][3] = As[(r + 8) * APITCH + k0 + q + 4];
            }
            uint32_t bfr[4][2];
            #pragma unroll
            for (int nt = 0; nt < 4; nt++) {
                const int n = wn * 32 + nt * 8 + g;
                // permuted layout: pair (k0+q, k0+q+4) contiguous -> one LDS.64
                uint2 p = *reinterpret_cast<const uint2*>(&Bs[n * BPITCH + k0 + q * 2]);
                bfr[nt][0] = p.x;
                bfr[nt][1] = p.y;
            }
            #pragma unroll
            for (int mt = 0; mt < 2; mt++)
                #pragma unroll
                for (int nt = 0; nt < 4; nt++)
                    mma8(acc[mt][nt], afr[mt], bfr[nt]);
        }
    }

    // ---- spill accumulators to smem z-tile [row][n], pitch ZPITCH ----
    __syncthreads();   // all warps done reading stage buffers (overlay reuse)
    #pragma unroll
    for (int mt = 0; mt < 2; mt++) {
        const int r0 = wm * 32 + mt * 16 + g;
        #pragma unroll
        for (int nt = 0; nt < 4; nt++) {
            const int n0 = wn * 32 + nt * 8 + 2 * q;
            *reinterpret_cast<float2*>(&sm[r0 * ZPITCH + n0]) =
                make_float2(acc[mt][nt][0], acc[mt][nt][1]);
            *reinterpret_cast<float2*>(&sm[(r0 + 8) * ZPITCH + n0]) =
                make_float2(acc[mt][nt][2], acc[mt][nt][3]);
        }
    }
    __syncthreads();

    // ---- fused LSTM epilogue: 256 rows x 32 j's, fully coalesced ----
    const int jl = lane;
    const int jg = j0 + jl;
    const float Bi = __ldg(bi + jg);
    const float Bf = __ldg(bf + jg);
    const float Bg = __ldg(bg + jg);
    const float Bo = __ldg(bo + jg);
    float* hout = out;
    float* cout = out + (size_t)BATCH * HD;

    #pragma unroll 4
    for (int it = 0; it < 8; it++) {
        const int row = it * 32 + wid;
        float4 z = *reinterpret_cast<const float4*>(&sm[row * ZPITCH + 4 * jl]);
        const float zi = z.x + Bi;
        const float zf = z.y + Bf;
        const float zg = z.z + Bg;
        const float zo = z.w + Bo;
        const float ig = fast_sigmoid(zi);
        const float fg = fast_sigmoid(zf);
        const float og = fast_sigmoid(zo);
        const float cc = fast_tanh(zg);
        const size_t go = (size_t)(m0 + row) * HD + jg;
        const float c0 = __ldg(cprev + go);
        const float cn = fg * c0 + ig * cc;
        const float hn = og * fast_tanh(cn);
        hout[go] = hn;
        cout[go] = cn;
    }
}

// ---------------- launch ----------------
extern "C" void kernel_launch(void* const* d_in, const int* in_sizes, int n_in,
                              void* d_out, int out_size)
{
    const float* x  = (const float*)d_in[0];
    const float* hp = (const float*)d_in[1];
    const float* cp = (const float*)d_in[2];
    const float* Wi = (const float*)d_in[3];
    const float* Ui = (const float*)d_in[4];
    const float* bi = (const float*)d_in[5];
    const float* Wf = (const float*)d_in[6];
    const float* Uf = (const float*)d_in[7];
    const float* bf = (const float*)d_in[8];
    const float* Wg = (const float*)d_in[9];
    const float* Ug = (const float*)d_in[10];
    const float* bg = (const float*)d_in[11];
    const float* Wo = (const float*)d_in[12];
    const float* Uo = (const float*)d_in[13];
    const float* bo = (const float*)d_in[14];
    float* out = (float*)d_out;

    cudaFuncSetAttribute(lstm_kernel, cudaFuncAttributeMaxDynamicSharedMemorySize, SM_BYTES);

    prep_weights_kernel<<<256, 512>>>(Wi, Ui, Wf, Uf, Wg, Ug, Wo, Uo);
    lstm_kernel<<<(BATCH / BM) * 4, NTHR, SM_BYTES>>>(x, hp, cp, bi, bf, bg, bo, out);
}

// round 5
// speedup vs baseline: 1.5553x; 1.1850x over previous
#include <cuda_runtime.h>
#include <cstdint>
#include <cstddef>

#define DI __device__ __forceinline__

// ---------------- problem constants ----------------
constexpr int BATCH = 131072;
constexpr int HD    = 128;       // H == IN == 128
constexpr int KTOT  = 256;       // x(128) ++ h_prev(128)
constexpr int BM    = 128;       // batch rows per CTA
constexpr int BN    = 128;       // gate-columns per CTA (32 j's x 4 gates, interleaved)
constexpr int KC    = 32;        // fp32 K per stage
constexpr int NKCH  = KTOT / KC; // 8
constexpr int NTHR  = 512;       // 16 warps: 4(m) x 4(n), warp tile 32x32
constexpr int NSTG  = 2;         // double buffer

// smem (floats)
constexpr int APITCH = 36;                    // A pitch: bank = 4g+q, conflict-free LDS.32
constexpr int BPITCH = 40;                    // B pitch: dbank = 4g+q, conflict-free LDS.64
constexpr int A_FL   = BM * APITCH;           // 4608
constexpr int B_FL   = BN * BPITCH;           // 5120
constexpr int STG_FL = A_FL + B_FL;           // 9728
constexpr int ZPITCH = 136;
constexpr int Z_FL   = BM * ZPITCH;           // 17408 fl = 69632 B (overlays 2-stage region)
constexpr int SM_BYTES = NSTG * STG_FL * 4;   // 77824 B -> 2 CTAs/SM

// weights: transposed + gate-interleaved (n = 4*j + gate) + fragment-pair-permuted k,
// tf32(rna)-rounded. [n=512][k'=256]
static __device__ float g_Bt[512 * KTOT];

// ---------------- PTX helpers ----------------
DI void cp_async16(void* dst, const void* src) {
    uint32_t a;
    asm("{ .reg .u64 t; cvta.to.shared.u64 t, %1; cvt.u32.u64 %0, t; }" : "=r"(a) : "l"(dst));
    asm volatile("cp.async.cg.shared.global [%0], [%1], 16;" :: "r"(a), "l"(src));
}
DI void cp_commit() { asm volatile("cp.async.commit_group;" ::: "memory"); }
template<int N> DI void cp_wait() { asm volatile("cp.async.wait_group %0;" :: "n"(N) : "memory"); }

DI uint32_t cvt_tf32(float v) {
    uint32_t t;
    asm("cvt.rna.tf32.f32 %0, %1;" : "=r"(t) : "f"(v));
    return t;
}
DI void mma8(float* d, const uint32_t* a, const uint32_t* b) {
    asm volatile("mma.sync.aligned.m16n8k8.row.col.f32.tf32.tf32.f32 "
        "{%0,%1,%2,%3}, {%4,%5,%6,%7}, {%8,%9}, {%0,%1,%2,%3};"
        : "+f"(d[0]), "+f"(d[1]), "+f"(d[2]), "+f"(d[3])
        : "r"(a[0]), "r"(a[1]), "r"(a[2]), "r"(a[3]), "r"(b[0]), "r"(b[1]));
}
DI float fast_sigmoid(float z) { return 1.0f / (1.0f + __expf(-z)); }
DI float fast_tanh(float z)    { float e = __expf(-2.0f * z); return (1.0f - e) / (1.0f + e); }

// ---------------- prologue: transpose + interleave + permute + tf32-round ----------------
// g_Bt[n][kp]: kp = chunk*32 + ks*8 + q*2 + h  <->  k = chunk*32 + ks*8 + q + 4*h
__global__ void prep_weights_kernel(
    const float* __restrict__ Wi, const float* __restrict__ Ui,
    const float* __restrict__ Wf, const float* __restrict__ Uf,
    const float* __restrict__ Wg, const float* __restrict__ Ug,
    const float* __restrict__ Wo, const float* __restrict__ Uo)
{
    int idx = blockIdx.x * blockDim.x + threadIdx.x;  // 0 .. 131071
    int kp   = idx & 255;
    int row  = idx >> 8;          // n = 4*j + gate
    int j    = row >> 2;
    int gate = row & 3;
    int chunk = kp >> 5;
    int r5    = kp & 31;
    int ks    = r5 >> 3;
    int t     = r5 & 7;
    int q     = t >> 1;
    int h     = t & 1;
    int k     = chunk * 32 + ks * 8 + q + 4 * h;
    const float* W = (gate == 0) ? Wi : (gate == 1) ? Wf : (gate == 2) ? Wg : Wo;
    const float* U = (gate == 0) ? Ui : (gate == 1) ? Uf : (gate == 2) ? Ug : Uo;
    float v = (k < HD) ? W[k * HD + j] : U[(k - HD) * HD + j];
    reinterpret_cast<uint32_t*>(g_Bt)[row * KTOT + kp] = cvt_tf32(v);
}

// ---------------- stage loader ----------------
DI void load_stage(float* sm, int buf, int s,
                   const float* __restrict__ x, const float* __restrict__ hp,
                   int m0, int n0w, int tid)
{
    float* As = sm + buf * STG_FL;
    float* Bs = As + A_FL;
    const float* asrc = (s < 4) ? x : hp;
    int kc = (s & 3) * KC;
    // A: 128 rows x 32 f32 = 1024 float4 -> 2 per thread (natural k order)
    #pragma unroll
    for (int i = 0; i < 2; i++) {
        int t  = tid + i * NTHR;
        int r  = t >> 3, c4 = t & 7;
        cp_async16(As + r * APITCH + c4 * 4,
                   asrc + (size_t)(m0 + r) * HD + kc + c4 * 4);
    }
    // B: 128 rows x 32 f32 = 1024 float4 -> 2 per thread (pre-permuted k order)
    #pragma unroll
    for (int i = 0; i < 2; i++) {
        int t  = tid + i * NTHR;
        int r  = t >> 3, c4 = t & 7;
        cp_async16(Bs + r * BPITCH + c4 * 4,
                   g_Bt + (size_t)(n0w + r) * KTOT + s * KC + c4 * 4);
    }
    cp_commit();
}

// ---------------- main fused kernel ----------------
__global__ void __launch_bounds__(NTHR, 2) lstm_kernel(
    const float* __restrict__ x, const float* __restrict__ hp,
    const float* __restrict__ cprev,
    const float* __restrict__ bi, const float* __restrict__ bf,
    const float* __restrict__ bg, const float* __restrict__ bo,
    float* __restrict__ out)
{
    extern __shared__ float sm[];
    const int tid  = threadIdx.x;
    const int lane = tid & 31;
    const int wid  = tid >> 5;
    const int wm   = wid & 3;        // warp m-index (4)
    const int wn   = wid >> 2;       // warp n-index (4)
    const int q    = lane & 3;
    const int g    = lane >> 2;

    const int mblk = blockIdx.x >> 2;
    const int nblk = blockIdx.x & 3;
    const int m0   = mblk * BM;
    const int n0w  = nblk * BN;      // weight-row base (interleaved n)
    const int j0   = nblk * 32;      // hidden-unit base

    float acc[2][4][4];
    #pragma unroll
    for (int a = 0; a < 2; a++)
        #pragma unroll
        for (int b = 0; b < 4; b++)
            #pragma unroll
            for (int c = 0; c < 4; c++) acc[a][b][c] = 0.0f;

    // ---- double-buffered pipelined GEMM over 8 K-chunks ----
    load_stage(sm, 0, 0, x, hp, m0, n0w, tid);
    load_stage(sm, 1, 1, x, hp, m0, n0w, tid);

    #pragma unroll
    for (int s = 0; s < NKCH; s++) {
        const int buf = s & 1;
        if (s < NKCH - 1) cp_wait<1>(); else cp_wait<0>();
        __syncthreads();                     // stage-s data visible to all

        const uint32_t* As = reinterpret_cast<const uint32_t*>(sm + buf * STG_FL);
        const uint32_t* Bs = As + A_FL;

        #pragma unroll
        for (int ks = 0; ks < 4; ks++) {
            const int k0 = ks * 8;
            uint32_t afr[2][4];
            #pragma unroll
            for (int mt = 0; mt < 2; mt++) {
                const int r = wm * 32 + mt * 16 + g;
                afr[mt][0] = As[r * APITCH + k0 + q];            // raw fp32 bits as tf32
                afr[mt][1] = As[(r + 8) * APITCH + k0 + q];
                afr[mt][2] = As[r * APITCH + k0 + q + 4];
                afr[mt][3] = As[(r + 8) * APITCH + k0 + q + 4];
            }
            uint32_t bfr[4][2];
            #pragma unroll
            for (int nt = 0; nt < 4; nt++) {
                const int n = wn * 32 + nt * 8 + g;
                // permuted layout: pair (k0+q, k0+q+4) contiguous -> one LDS.64
                uint2 p = *reinterpret_cast<const uint2*>(&Bs[n * BPITCH + k0 + q * 2]);
                bfr[nt][0] = p.x;
                bfr[nt][1] = p.y;
            }
            #pragma unroll
            for (int mt = 0; mt < 2; mt++)
                #pragma unroll
                for (int nt = 0; nt < 4; nt++)
                    mma8(acc[mt][nt], afr[mt], bfr[nt]);
        }

        __syncthreads();                     // buffer s&1 free for overwrite
        if (s + 2 < NKCH) load_stage(sm, buf, s + 2, x, hp, m0, n0w, tid);
    }

    // ---- spill accumulators to smem z-tile [row][n], pitch ZPITCH ----
    #pragma unroll
    for (int mt = 0; mt < 2; mt++) {
        const int r0 = wm * 32 + mt * 16 + g;
        #pragma unroll
        for (int nt = 0; nt < 4; nt++) {
            const int n0 = wn * 32 + nt * 8 + 2 * q;
            *reinterpret_cast<float2*>(&sm[r0 * ZPITCH + n0]) =
                make_float2(acc[mt][nt][0], acc[mt][nt][1]);
            *reinterpret_cast<float2*>(&sm[(r0 + 8) * ZPITCH + n0]) =
                make_float2(acc[mt][nt][2], acc[mt][nt][3]);
        }
    }
    __syncthreads();

    // ---- fused LSTM epilogue: 128 rows x 32 j's, fully coalesced ----
    const int jl = lane;
    const int jg = j0 + jl;
    const float Bi = __ldg(bi + jg);
    const float Bf = __ldg(bf + jg);
    const float Bg = __ldg(bg + jg);
    const float Bo = __ldg(bo + jg);
    float* hout = out;
    float* cout = out + (size_t)BATCH * HD;

    #pragma unroll 4
    for (int it = 0; it < 8; it++) {
        const int row = it * 16 + wid;
        float4 z = *reinterpret_cast<const float4*>(&sm[row * ZPITCH + 4 * jl]);
        const float zi = z.x + Bi;
        const float zf = z.y + Bf;
        const float zg = z.z + Bg;
        const float zo = z.w + Bo;
        const float ig = fast_sigmoid(zi);
        const float fg = fast_sigmoid(zf);
        const float og = fast_sigmoid(zo);
        const float cc = fast_tanh(zg);
        const size_t go = (size_t)(m0 + row) * HD + jg;
        const float c0 = __ldg(cprev + go);
        const float cn = fg * c0 + ig * cc;
        const float hn = og * fast_tanh(cn);
        hout[go] = hn;
        cout[go] = cn;
    }
}

// ---------------- launch ----------------
extern "C" void kernel_launch(void* const* d_in, const int* in_sizes, int n_in,
                              void* d_out, int out_size)
{
    const float* x  = (const float*)d_in[0];
    const float* hp = (const float*)d_in[1];
    const float* cp = (const float*)d_in[2];
    const float* Wi = (const float*)d_in[3];
    const float* Ui = (const float*)d_in[4];
    const float* bi = (const float*)d_in[5];
    const float* Wf = (const float*)d_in[6];
    const float* Uf = (const float*)d_in[7];
    const float* bf = (const float*)d_in[8];
    const float* Wg = (const float*)d_in[9];
    const float* Ug = (const float*)d_in[10];
    const float* bg = (const float*)d_in[11];
    const float* Wo = (const float*)d_in[12];
    const float* Uo = (const float*)d_in[13];
    const float* bo = (const float*)d_in[14];
    float* out = (float*)d_out;

    cudaFuncSetAttribute(lstm_kernel, cudaFuncAttributeMaxDynamicSharedMemorySize, SM_BYTES);

    prep_weights_kernel<<<256, 512>>>(Wi, Ui, Wf, Uf, Wg, Ug, Wo, Uo);
    lstm_kernel<<<(BATCH / BM) * 4, NTHR, SM_BYTES>>>(x, hp, cp, bi, bf, bg, bo, out);
}